// round 14
// baseline (speedup 1.0000x reference)
#include <cuda_runtime.h>
#include <math.h>

#define BB 4
#define CC 8
#define HH 256
#define WW 256
#define INF_D 512
#define JT 8                          // columns per colin tile
#define NR 8                          // rows per colin thread (interleaved)
#define JTO 2                         // columns per colout tile
#define NRO 2                         // rows per colout thread
#define NIN   (BB*CC*(WW/JT))         // 1024 colin blocks
#define NOUT  (BB*(WW/JTO))           // 512 colout blocks
#define NCOL  (NIN + NOUT)            // 1536 k_col blocks = 48 leaves x 32
#define NLEAF (NCOL/32)               // 48
#define NROWB (BB*HH)                 // 1024 rowpass blocks
#define NSMB  ((BB*HH*WW)/(4*256))    // 256 softmax blocks (float4, 256 thr)

// Static device scratch (no allocations allowed). Zero-initialized at load;
// k_col's elected block restores g_cnt/g_sem* to 0 every launch, so graph
// replays see identical initial state.
__device__ unsigned short g_gin[BB*CC*HH*WW];   // 4 MB
__device__ unsigned short g_tr[BB*HH*WW];       // 0.5 MB: packed (t<<10 | r)
__device__ float          g_prob[BB*CC*HH*WW];  // 8 MB
__device__ int            g_cnt[BB*CC];
__device__ float          g_part[NCOL];
__device__ int            g_sem1[NLEAF];        // leaf arrival counters
__device__ int            g_sem2;               // root arrival counter

// ---------------------------------------------------------------------------
__device__ __forceinline__ int nearest_bit(const unsigned* wd, unsigned inv, int j) {
    const int wj = j >> 5, bj = j & 31;
    const unsigned cur = wd[wj] ^ inv;
    int dl = INF_D, dr = INF_D;

    unsigned m = cur & (0xffffffffu >> (31 - bj));
    if (m) {
        dl = bj - (31 - __clz(m));
    } else {
        #pragma unroll
        for (int w = 6; w >= 0; --w) {
            if (w < wj) {
                const unsigned mw = wd[w] ^ inv;
                if (mw) { dl = j - (w*32 + 31 - __clz(mw)); break; }
            }
        }
    }
    m = cur >> bj;
    if (m) {
        dr = __ffs(m) - 1;
    } else {
        #pragma unroll
        for (int w = 1; w <= 7; ++w) {
            if (w > wj) {
                const unsigned mw = wd[w] ^ inv;
                if (mw) { dr = (w*32 + __ffs(mw) - 1) - j; break; }
            }
        }
    }
    int d = dl < dr ? dl : dr;
    return d < INF_D ? d : INF_D;
}

// Pre-pass: blocks [0, NROWB) bitmask row pass; [NROWB, +NSMB) float4 softmax.
__global__ void k_pre(const int* __restrict__ target,
                      const float* __restrict__ output) {
    if (blockIdx.x < NROWB) {
        const int row = blockIdx.x;
        const int b   = row >> 8;
        const int h   = row & 255;
        const int j   = threadIdx.x;
        const int w   = j >> 5;
        const int ln  = j & 31;

        __shared__ unsigned mask[CC][8];
        const int t = target[row * WW + j];

        #pragma unroll
        for (int c = 0; c < CC; ++c) {
            const unsigned m = __ballot_sync(0xffffffffu, t == c);
            if (ln == 0) mask[c][w] = m;
        }
        __syncthreads();

        const int r = nearest_bit(mask[t], 0xffffffffu, j);
        g_tr[row * WW + j] = (unsigned short)(r | (t << 10));

        #pragma unroll
        for (int c = 0; c < CC; ++c) {
            const int g = nearest_bit(mask[c], 0u, j);
            g_gin[((b*CC + c)*HH + h)*WW + j] = (unsigned short)g;
        }

        if (j < CC) {
            int cnt = 0;
            #pragma unroll
            for (int k = 0; k < 8; ++k) cnt += __popc(mask[j][k]);
            if (cnt) atomicAdd(&g_cnt[b*CC + j], cnt);
        }
    } else {
        const int q   = (blockIdx.x - NROWB) * 256 + threadIdx.x;
        const int b   = q >> 14;
        const int hw4 = q & 16383;
        const float4* out4 = (const float4*)output;
        float4* prob4 = (float4*)g_prob;

        float4 lg[CC];
        float mx = -1e30f, my = -1e30f, mz = -1e30f, mw = -1e30f;
        #pragma unroll
        for (int c = 0; c < CC; ++c) {
            lg[c] = out4[(b*CC + c)*16384 + hw4];
            mx = fmaxf(mx, lg[c].x); my = fmaxf(my, lg[c].y);
            mz = fmaxf(mz, lg[c].z); mw = fmaxf(mw, lg[c].w);
        }
        float sx = 0.f, sy = 0.f, sz = 0.f, sw = 0.f;
        #pragma unroll
        for (int c = 0; c < CC; ++c) {
            lg[c].x = __expf(lg[c].x - mx); sx += lg[c].x;
            lg[c].y = __expf(lg[c].y - my); sy += lg[c].y;
            lg[c].z = __expf(lg[c].z - mz); sz += lg[c].z;
            lg[c].w = __expf(lg[c].w - mw); sw += lg[c].w;
        }
        const float ix = 1.f/sx, iy = 1.f/sy, iz = 1.f/sz, iw = 1.f/sw;
        #pragma unroll
        for (int c = 0; c < CC; ++c)
            prob4[(b*CC + c)*16384 + hw4] =
                make_float4(lg[c].x*ix, lg[c].y*iy, lg[c].z*iz, lg[c].w*iw);
    }
}

// Deterministic block reduce into *dst (thread 0 writes).
__device__ __forceinline__ void block_reduce_write(float acc, float* dst) {
    #pragma unroll
    for (int o = 16; o > 0; o >>= 1)
        acc += __shfl_xor_sync(0xffffffffu, acc, o);
    __shared__ float swarp[8];
    if ((threadIdx.x & 31) == 0) swarp[threadIdx.x >> 5] = acc;
    __syncthreads();
    if (threadIdx.x == 0) {
        float s0 = 0.f;
        #pragma unroll
        for (int w = 0; w < 8; ++w) s0 += swarp[w];
        *dst = s0;
    }
}

// Merged column pass + hierarchical last-block final reduction.
__global__ void k_col(float* __restrict__ out) {
    __shared__ float s[HH*JT];                  // 8 KB, aliased by both paths
    float acc = 0.0f;

    if (blockIdx.x < NIN) {
        // ---------------- inside transform ----------------
        const int jt  = blockIdx.x & (WW/JT - 1);
        const int bc  = blockIdx.x / (WW/JT);
        const int j0  = jt * JT;

        if (g_cnt[bc] != 0) {
            const int jj = threadIdx.x & (JT - 1);
            const int k0 = threadIdx.x / JT;    // 0..31

            #pragma unroll
            for (int m = 0; m < NR; ++m) {
                const int k = k0 + 32*m;
                const float g = (float)g_gin[(bc*HH + k)*WW + j0 + jj];
                s[k*JT + jj] = g * g;
            }
            __syncthreads();

            float din2[NR], vlo[NR], vhi[NR];
            #pragma unroll
            for (int r = 0; r < NR; ++r) {
                const int i = k0 + 32*r;
                din2[r] = s[i*JT + jj];
                vlo[r]  = (i-1 >= 0) ? s[(i-1)*JT + jj] : 1e9f;
                vhi[r]  = (i+1 < HH) ? s[(i+1)*JT + jj] : 1e9f;
            }
            float mx = 0.f;
            #pragma unroll
            for (int r = 0; r < NR; ++r) mx = fmaxf(mx, din2[r]);

            for (int d = 1; d < HH; ++d) {
                const float dd2 = (float)(d * d);
                if (dd2 >= mx) break;
                #pragma unroll
                for (int r = 0; r < NR; ++r)
                    din2[r] = fminf(din2[r], dd2 + fminf(vlo[r], vhi[r]));
                #pragma unroll
                for (int r = 0; r < NR; ++r) {  // prefetch step d+1
                    const int i  = k0 + 32*r;
                    const int lo = i - d - 1, hi = i + d + 1;
                    vlo[r] = (lo >= 0) ? s[lo*JT + jj] : 1e9f;
                    vhi[r] = (hi < HH) ? s[hi*JT + jj] : 1e9f;
                }
                mx = 0.f;
                #pragma unroll
                for (int r = 0; r < NR; ++r) mx = fmaxf(mx, din2[r]);
            }

            #pragma unroll
            for (int r = 0; r < NR; ++r) {
                const int i = k0 + 32*r;
                acc += sqrtf(din2[r]) * g_prob[(bc*HH + i)*WW + j0 + jj];
            }
        }
    } else {
        // ------------- outside transform (collapsed) -------------
        const int bid = blockIdx.x - NIN;       // 0..511
        const int jt  = bid & (WW/JTO - 1);
        const int b   = bid / (WW/JTO);
        const int j0  = jt * JTO;

        int* si = (int*)s;
        const int jj = threadIdx.x & (JTO - 1);
        const int k0 = threadIdx.x / JTO;       // 0..127

        #pragma unroll
        for (int m = 0; m < NRO; ++m) {
            const int k = k0 + 128*m;
            const unsigned v = g_tr[(b*HH + k)*WW + j0 + jj];
            const int rr = (int)(v & 1023u);
            si[k*JTO + jj] = (rr*rr*8) | (int)(v >> 10);   // r^2<<3 | t
        }
        __syncthreads();

        float dout2[NRO];
        int   tc[NRO], plo[NRO], phi[NRO];
        #pragma unroll
        for (int r = 0; r < NRO; ++r) {
            const int i  = k0 + 128*r;
            const int pv = si[i*JTO + jj];
            tc[r]    = pv & 7;
            dout2[r] = (float)(pv >> 3);
            plo[r]   = (i-1 >= 0) ? si[(i-1)*JTO + jj] : -1;
            phi[r]   = (i+1 < HH) ? si[(i+1)*JTO + jj] : -1;
        }
        float mx = 0.f;
        #pragma unroll
        for (int r = 0; r < NRO; ++r) mx = fmaxf(mx, dout2[r]);

        for (int d = 1; d < HH; ++d) {
            const float dd2 = (float)(d * d);
            if (dd2 >= mx) break;
            #pragma unroll
            for (int r = 0; r < NRO; ++r) {
                const float vl = (plo[r] < 0) ? 1e9f
                               : (((plo[r] & 7) == tc[r]) ? (float)(plo[r] >> 3) : 0.0f);
                const float vh = (phi[r] < 0) ? 1e9f
                               : (((phi[r] & 7) == tc[r]) ? (float)(phi[r] >> 3) : 0.0f);
                dout2[r] = fminf(dout2[r], dd2 + fminf(vl, vh));
            }
            #pragma unroll
            for (int r = 0; r < NRO; ++r) {
                const int i  = k0 + 128*r;
                const int lo = i - d - 1, hi = i + d + 1;
                plo[r] = (lo >= 0) ? si[lo*JTO + jj] : -1;
                phi[r] = (hi < HH) ? si[hi*JTO + jj] : -1;
            }
            mx = 0.f;
            #pragma unroll
            for (int r = 0; r < NRO; ++r) mx = fmaxf(mx, dout2[r]);
        }

        #pragma unroll
        for (int r = 0; r < NRO; ++r) {
            const int i = k0 + 128*r;
            const float p = g_prob[((b*CC + tc[r])*HH + i)*WW + j0 + jj];
            acc -= sqrtf(dout2[r]) * p;
        }
    }

    __syncthreads();
    block_reduce_write(acc, &g_part[blockIdx.x]);

    // ----- hierarchical rendezvous: 48 leaves x 32, then root of 48 -----
    __shared__ int s_last;
    if (threadIdx.x == 0) {
        __threadfence();                               // release g_part write
        int last = 0;
        const int leaf = blockIdx.x >> 5;              // 0..47
        if (atomicAdd(&g_sem1[leaf], 1) == 31) {       // last of 32 in leaf
            __threadfence();                           // acquire leaf, release to root
            if (atomicAdd(&g_sem2, 1) == NLEAF - 1) {  // last leaf
                __threadfence();                       // acquire all g_part
                last = 1;
            }
        }
        s_last = last;
    }
    __syncthreads();
    if (!s_last) return;

    // ----- elected block: deterministic fixed-order final sum -----
    float v = 0.0f;
    for (int k = threadIdx.x; k < NCOL; k += 256)
        v += g_part[k];
    #pragma unroll
    for (int o = 16; o > 0; o >>= 1)
        v += __shfl_xor_sync(0xffffffffu, v, o);
    __shared__ float fw[8];
    if ((threadIdx.x & 31) == 0) fw[threadIdx.x >> 5] = v;
    __syncthreads();
    if (threadIdx.x == 0) {
        float total = 0.f;
        #pragma unroll
        for (int w = 0; w < 8; ++w) total += fw[w];
        int n = 0;
        #pragma unroll
        for (int k = 0; k < BB*CC; ++k) n += (g_cnt[k] > 0) ? 1 : 0;
        const float nf = (n > 0) ? (float)n : 1.0f;
        out[0] = total / nf;
        // reset state for next graph replay
        #pragma unroll
        for (int k = 0; k < BB*CC; ++k) g_cnt[k] = 0;
        g_sem2 = 0;
    }
    if (threadIdx.x < NLEAF) g_sem1[threadIdx.x] = 0;
}

// ---------------------------------------------------------------------------
extern "C" void kernel_launch(void* const* d_in, const int* in_sizes, int n_in,
                              void* d_out, int out_size) {
    const float* output = (const float*)d_in[0];   // [4,8,256,256] fp32
    const int*   target = (const int*)d_in[1];     // [4,256,256] int32
    float*       out    = (float*)d_out;           // scalar

    k_pre<<<NROWB + NSMB, 256>>>(target, output);
    k_col<<<NCOL, 256>>>(out);
}

// round 15
// speedup vs baseline: 1.0526x; 1.0526x over previous
#include <cuda_runtime.h>
#include <math.h>

#define BB 4
#define CC 8
#define HH 256
#define WW 256
#define INF_D 512
#define JT 8                          // columns per colin tile
#define NR 8                          // rows per colin thread (interleaved)
#define JTO 2                         // columns per colout tile
#define NRO 2                         // rows per colout thread
#define PAD 255                       // sentinel rows each side (colin)
#define SROWS (HH + 2*PAD)            // 766 padded rows
#define NIN   (BB*CC*(WW/JT))         // 1024 colin blocks
#define NOUT  (BB*(WW/JTO))           // 512 colout blocks
#define NCOL  (NIN + NOUT)            // 1536 k_col blocks
#define NROWB (BB*HH)                 // 1024 rowpass blocks
#define NSMB  ((BB*HH*WW)/(4*256))    // 256 softmax blocks

// Static device scratch (no allocations allowed). Zero-initialized at load;
// k_final resets g_cnt each launch -> graph replays see identical state.
__device__ unsigned short g_gin[BB*CC*HH*WW];   // 4 MB
__device__ unsigned short g_tr[BB*HH*WW];       // 0.5 MB: packed (t<<10 | r)
__device__ float          g_prob[BB*CC*HH*WW];  // 8 MB
__device__ int            g_cnt[BB*CC];
__device__ float          g_part[NCOL];

// ---------------------------------------------------------------------------
__device__ __forceinline__ int nearest_bit(const unsigned* wd, unsigned inv, int j) {
    const int wj = j >> 5, bj = j & 31;
    const unsigned cur = wd[wj] ^ inv;
    int dl = INF_D, dr = INF_D;

    unsigned m = cur & (0xffffffffu >> (31 - bj));
    if (m) {
        dl = bj - (31 - __clz(m));
    } else {
        #pragma unroll
        for (int w = 6; w >= 0; --w) {
            if (w < wj) {
                const unsigned mw = wd[w] ^ inv;
                if (mw) { dl = j - (w*32 + 31 - __clz(mw)); break; }
            }
        }
    }
    m = cur >> bj;
    if (m) {
        dr = __ffs(m) - 1;
    } else {
        #pragma unroll
        for (int w = 1; w <= 7; ++w) {
            if (w > wj) {
                const unsigned mw = wd[w] ^ inv;
                if (mw) { dr = (w*32 + __ffs(mw) - 1) - j; break; }
            }
        }
    }
    int d = dl < dr ? dl : dr;
    return d < INF_D ? d : INF_D;
}

// Pre-pass: blocks [0, NROWB) bitmask row pass; [NROWB, +NSMB) float4 softmax.
// g_cnt is zeroed by the PREVIOUS launch's k_final (or load-time init).
__global__ void k_pre(const int* __restrict__ target,
                      const float* __restrict__ output) {
    if (blockIdx.x < NROWB) {
        const int row = blockIdx.x;
        const int b   = row >> 8;
        const int h   = row & 255;
        const int j   = threadIdx.x;
        const int w   = j >> 5;
        const int ln  = j & 31;

        __shared__ unsigned mask[CC][8];
        const int t = target[row * WW + j];

        #pragma unroll
        for (int c = 0; c < CC; ++c) {
            const unsigned m = __ballot_sync(0xffffffffu, t == c);
            if (ln == 0) mask[c][w] = m;
        }
        __syncthreads();

        const int r = nearest_bit(mask[t], 0xffffffffu, j);
        g_tr[row * WW + j] = (unsigned short)(r | (t << 10));

        #pragma unroll
        for (int c = 0; c < CC; ++c) {
            const int g = nearest_bit(mask[c], 0u, j);
            g_gin[((b*CC + c)*HH + h)*WW + j] = (unsigned short)g;
        }

        if (j < CC) {
            int cnt = 0;
            #pragma unroll
            for (int k = 0; k < 8; ++k) cnt += __popc(mask[j][k]);
            if (cnt) atomicAdd(&g_cnt[b*CC + j], cnt);
        }
    } else {
        const int q   = (blockIdx.x - NROWB) * 256 + threadIdx.x;
        const int b   = q >> 14;
        const int hw4 = q & 16383;
        const float4* out4 = (const float4*)output;
        float4* prob4 = (float4*)g_prob;

        float4 lg[CC];
        float mx = -1e30f, my = -1e30f, mz = -1e30f, mw = -1e30f;
        #pragma unroll
        for (int c = 0; c < CC; ++c) {
            lg[c] = out4[(b*CC + c)*16384 + hw4];
            mx = fmaxf(mx, lg[c].x); my = fmaxf(my, lg[c].y);
            mz = fmaxf(mz, lg[c].z); mw = fmaxf(mw, lg[c].w);
        }
        float sx = 0.f, sy = 0.f, sz = 0.f, sw = 0.f;
        #pragma unroll
        for (int c = 0; c < CC; ++c) {
            lg[c].x = __expf(lg[c].x - mx); sx += lg[c].x;
            lg[c].y = __expf(lg[c].y - my); sy += lg[c].y;
            lg[c].z = __expf(lg[c].z - mz); sz += lg[c].z;
            lg[c].w = __expf(lg[c].w - mw); sw += lg[c].w;
        }
        const float ix = 1.f/sx, iy = 1.f/sy, iz = 1.f/sz, iw = 1.f/sw;
        #pragma unroll
        for (int c = 0; c < CC; ++c)
            prob4[(b*CC + c)*16384 + hw4] =
                make_float4(lg[c].x*ix, lg[c].y*iy, lg[c].z*iz, lg[c].w*iw);
    }
}

// Deterministic block reduce into *dst (thread 0 writes).
__device__ __forceinline__ void block_reduce_write(float acc, float* dst) {
    #pragma unroll
    for (int o = 16; o > 0; o >>= 1)
        acc += __shfl_xor_sync(0xffffffffu, acc, o);
    __shared__ float swarp[8];
    if ((threadIdx.x & 31) == 0) swarp[threadIdx.x >> 5] = acc;
    __syncthreads();
    if (threadIdx.x == 0) {
        float s0 = 0.f;
        #pragma unroll
        for (int w = 0; w < 8; ++w) s0 += swarp[w];
        *dst = s0;
    }
}

// Merged column pass. Blocks [0, NIN): inside transform with SENTINEL-PADDED
// smem (no bounds checks; two walking pointers with immediate offsets).
// Blocks [NIN, NCOL): class-collapsed outside transform (guarded, cheap).
__global__ void k_col() {
    __shared__ float s2[SROWS*JT];              // 24.5 KB (colin); colout uses prefix
    float acc = 0.0f;

    if (blockIdx.x < NIN) {
        // ---------------- inside transform ----------------
        const int jt  = blockIdx.x & (WW/JT - 1);
        const int bc  = blockIdx.x / (WW/JT);
        const int j0  = jt * JT;

        if (g_cnt[bc] != 0) {
            const int jj = threadIdx.x & (JT - 1);
            const int k0 = threadIdx.x / JT;    // 0..31

            // sentinel pads: rows [0,PAD) and [PAD+HH, SROWS)
            for (int idx = threadIdx.x; idx < PAD*JT; idx += 256) {
                s2[idx] = 1e9f;
                s2[(PAD+HH)*JT + idx] = 1e9f;
            }
            #pragma unroll
            for (int m = 0; m < NR; ++m) {
                const int k = k0 + 32*m;
                const float g = (float)g_gin[(bc*HH + k)*WW + j0 + jj];
                s2[(k + PAD)*JT + jj] = g * g;
            }
            __syncthreads();

            float din2[NR], vlo[NR], vhi[NR];
            const float* plo = &s2[(k0 + PAD - 1)*JT + jj];  // row i-1
            const float* phi = &s2[(k0 + PAD + 1)*JT + jj];  // row i+1
            #pragma unroll
            for (int r = 0; r < NR; ++r) {
                din2[r] = s2[(k0 + 32*r + PAD)*JT + jj];
                vlo[r]  = plo[r*32*JT];
                vhi[r]  = phi[r*32*JT];
            }
            float mx = 0.f;
            #pragma unroll
            for (int r = 0; r < NR; ++r) mx = fmaxf(mx, din2[r]);

            for (int d = 1; d < HH; ++d) {
                const float dd2 = (float)(d * d);
                if (dd2 >= mx) break;
                #pragma unroll
                for (int r = 0; r < NR; ++r)
                    din2[r] = fminf(din2[r], dd2 + fminf(vlo[r], vhi[r]));
                plo -= JT; phi += JT;                    // rows i-(d+1), i+(d+1)
                #pragma unroll
                for (int r = 0; r < NR; ++r) {           // prefetch step d+1
                    vlo[r] = plo[r*32*JT];
                    vhi[r] = phi[r*32*JT];
                }
                mx = 0.f;
                #pragma unroll
                for (int r = 0; r < NR; ++r) mx = fmaxf(mx, din2[r]);
            }

            #pragma unroll
            for (int r = 0; r < NR; ++r) {
                const int i = k0 + 32*r;
                acc += sqrtf(din2[r]) * g_prob[(bc*HH + i)*WW + j0 + jj];
            }
        }
    } else {
        // ------------- outside transform (collapsed) -------------
        const int bid = blockIdx.x - NIN;       // 0..511
        const int jt  = bid & (WW/JTO - 1);
        const int b   = bid / (WW/JTO);
        const int j0  = jt * JTO;

        int* si = (int*)s2;
        const int jj = threadIdx.x & (JTO - 1);
        const int k0 = threadIdx.x / JTO;       // 0..127

        #pragma unroll
        for (int m = 0; m < NRO; ++m) {
            const int k = k0 + 128*m;
            const unsigned v = g_tr[(b*HH + k)*WW + j0 + jj];
            const int rr = (int)(v & 1023u);
            si[k*JTO + jj] = (rr*rr*8) | (int)(v >> 10);   // r^2<<3 | t
        }
        __syncthreads();

        float dout2[NRO];
        int   tc[NRO], plo[NRO], phi[NRO];
        #pragma unroll
        for (int r = 0; r < NRO; ++r) {
            const int i  = k0 + 128*r;
            const int pv = si[i*JTO + jj];
            tc[r]    = pv & 7;
            dout2[r] = (float)(pv >> 3);
            plo[r]   = (i-1 >= 0) ? si[(i-1)*JTO + jj] : -1;
            phi[r]   = (i+1 < HH) ? si[(i+1)*JTO + jj] : -1;
        }
        float mx = 0.f;
        #pragma unroll
        for (int r = 0; r < NRO; ++r) mx = fmaxf(mx, dout2[r]);

        for (int d = 1; d < HH; ++d) {
            const float dd2 = (float)(d * d);
            if (dd2 >= mx) break;
            #pragma unroll
            for (int r = 0; r < NRO; ++r) {
                const float vl = (plo[r] < 0) ? 1e9f
                               : (((plo[r] & 7) == tc[r]) ? (float)(plo[r] >> 3) : 0.0f);
                const float vh = (phi[r] < 0) ? 1e9f
                               : (((phi[r] & 7) == tc[r]) ? (float)(phi[r] >> 3) : 0.0f);
                dout2[r] = fminf(dout2[r], dd2 + fminf(vl, vh));
            }
            #pragma unroll
            for (int r = 0; r < NRO; ++r) {
                const int i  = k0 + 128*r;
                const int lo = i - d - 1, hi = i + d + 1;
                plo[r] = (lo >= 0) ? si[lo*JTO + jj] : -1;
                phi[r] = (hi < HH) ? si[hi*JTO + jj] : -1;
            }
            mx = 0.f;
            #pragma unroll
            for (int r = 0; r < NRO; ++r) mx = fmaxf(mx, dout2[r]);
        }

        #pragma unroll
        for (int r = 0; r < NRO; ++r) {
            const int i = k0 + 128*r;
            const float p = g_prob[((b*CC + tc[r])*HH + i)*WW + j0 + jj];
            acc -= sqrtf(dout2[r]) * p;
        }
    }

    __syncthreads();
    block_reduce_write(acc, &g_part[blockIdx.x]);
}

// Final: sum 1536 partials in fixed order, divide by n, reset g_cnt for the
// next graph replay (reads complete before reset; single thread, ordered).
__global__ void k_final(float* __restrict__ out) {
    float v = 0.0f;
    for (int k = threadIdx.x; k < NCOL; k += 256)
        v += g_part[k];
    #pragma unroll
    for (int o = 16; o > 0; o >>= 1)
        v += __shfl_xor_sync(0xffffffffu, v, o);
    __shared__ float fw[8];
    if ((threadIdx.x & 31) == 0) fw[threadIdx.x >> 5] = v;
    __syncthreads();
    if (threadIdx.x == 0) {
        float total = 0.f;
        #pragma unroll
        for (int w = 0; w < 8; ++w) total += fw[w];
        int n = 0;
        #pragma unroll
        for (int k = 0; k < BB*CC; ++k) n += (g_cnt[k] > 0) ? 1 : 0;
        const float nf = (n > 0) ? (float)n : 1.0f;
        out[0] = total / nf;
        #pragma unroll
        for (int k = 0; k < BB*CC; ++k) g_cnt[k] = 0;   // reset for replay
    }
}

// ---------------------------------------------------------------------------
extern "C" void kernel_launch(void* const* d_in, const int* in_sizes, int n_in,
                              void* d_out, int out_size) {
    const float* output = (const float*)d_in[0];   // [4,8,256,256] fp32
    const int*   target = (const int*)d_in[1];     // [4,256,256] int32
    float*       out    = (float*)d_out;           // scalar

    k_pre  <<<NROWB + NSMB, 256>>>(target, output);
    k_col  <<<NCOL, 256>>>();
    k_final<<<1, 256>>>(out);
}

// round 16
// speedup vs baseline: 1.0702x; 1.0167x over previous
#include <cuda_runtime.h>
#include <math.h>

#define BB 4
#define CC 8
#define HH 256
#define WW 256
#define INF_D 512
#define JT 8                          // columns per colin tile
#define NR 8                          // rows per colin thread (interleaved)
#define JTO 2                         // columns per colout tile
#define NRO 2                         // rows per colout thread
#define PAD 255                       // sentinel rows each side (colin)
#define SROWS (HH + 2*PAD)            // 766 padded rows
#define NIN   (BB*CC*(WW/JT))         // 1024 colin blocks
#define NOUT  (BB*(WW/JTO))           // 512 colout blocks
#define NCOL  (NIN + NOUT)            // 1536 k_col blocks
#define NROWB (BB*HH)                 // 1024 rowpass blocks
#define NSMB  ((BB*HH*WW)/(4*256))    // 256 softmax blocks

// Static device scratch. Zero-init at load; k_col's elected block resets
// g_cnt / g_sem each launch -> graph replays see identical state.
__device__ unsigned short g_gin[BB*CC*HH*WW];   // 4 MB
__device__ unsigned short g_tr[BB*HH*WW];       // 0.5 MB: packed (t<<10 | r)
__device__ float          g_prob[BB*CC*HH*WW];  // 8 MB
__device__ int            g_cnt[BB*CC];
__device__ float          g_part[NCOL];
__device__ int            g_sem;

// ---------------------------------------------------------------------------
// Branchless nearest-set-bit query using per-(class,word) prefix/suffix LUT.
__device__ __forceinline__ int nb_lut(unsigned cur, int pref, int suff,
                                      int j, int bj) {
    const unsigned below = cur & (0xffffffffu >> (31 - bj));  // bits [0..bj]
    const unsigned above = cur >> bj;                         // bits [bj..31]
    const int dl = below ? (bj - (31 - __clz(below))) : (j - pref);
    const int dr = above ? (__ffs(above) - 1) : (suff - j);
    int d = dl < dr ? dl : dr;
    return d < INF_D ? d : INF_D;
}

// Pre-pass: blocks [0, NROWB) LUT row pass; [NROWB, +NSMB) float4 softmax.
__global__ void k_pre(const int* __restrict__ target,
                      const float* __restrict__ output) {
    if (blockIdx.x < NROWB) {
        const int row = blockIdx.x;
        const int b   = row >> 8;
        const int h   = row & 255;
        const int j   = threadIdx.x;
        const int w   = j >> 5;
        const int ln  = j & 31;
        const int wj  = j >> 5;
        const int bj  = j & 31;

        __shared__ unsigned mask[CC][8];
        __shared__ int pf[CC][8], sf[CC][8], pfN[CC][8], sfN[CC][8];
        const int t = target[row * WW + j];

        #pragma unroll
        for (int c = 0; c < CC; ++c) {
            const unsigned m = __ballot_sync(0xffffffffu, t == c);
            if (ln == 0) mask[c][w] = m;
        }
        __syncthreads();

        // 64 threads build the prefix/suffix LUTs (masks + complements).
        if (j < 64) {
            const int c = j >> 3, ww = j & 7;
            int p = -1024, pn = -1024;
            for (int u = 0; u < ww; ++u) {
                const unsigned m = mask[c][u], mn = ~m;
                if (m)  p  = u*32 + 31 - __clz(m);
                if (mn) pn = u*32 + 31 - __clz(mn);
            }
            pf[c][ww] = p;  pfN[c][ww] = pn;
            int s = 1 << 20, sn = 1 << 20;
            for (int u = 7; u > ww; --u) {
                const unsigned m = mask[c][u], mn = ~m;
                if (m)  s  = u*32 + __ffs(m) - 1;
                if (mn) sn = u*32 + __ffs(mn) - 1;
            }
            sf[c][ww] = s;  sfN[c][ww] = sn;
        }
        __syncthreads();

        // r: nearest different-class column  (complement of mask[t])
        const int r = nb_lut(~mask[t][wj], pfN[t][wj], sfN[t][wj], j, bj);
        g_tr[row * WW + j] = (unsigned short)(r | (t << 10));

        #pragma unroll
        for (int c = 0; c < CC; ++c) {
            const int g = nb_lut(mask[c][wj], pf[c][wj], sf[c][wj], j, bj);
            g_gin[((b*CC + c)*HH + h)*WW + j] = (unsigned short)g;
        }

        if (j < CC) {
            int cnt = 0;
            #pragma unroll
            for (int k = 0; k < 8; ++k) cnt += __popc(mask[j][k]);
            if (cnt) atomicAdd(&g_cnt[b*CC + j], cnt);
        }
    } else {
        const int q   = (blockIdx.x - NROWB) * 256 + threadIdx.x;
        const int b   = q >> 14;
        const int hw4 = q & 16383;
        const float4* out4 = (const float4*)output;
        float4* prob4 = (float4*)g_prob;

        float4 lg[CC];
        float mx = -1e30f, my = -1e30f, mz = -1e30f, mw = -1e30f;
        #pragma unroll
        for (int c = 0; c < CC; ++c) {
            lg[c] = out4[(b*CC + c)*16384 + hw4];
            mx = fmaxf(mx, lg[c].x); my = fmaxf(my, lg[c].y);
            mz = fmaxf(mz, lg[c].z); mw = fmaxf(mw, lg[c].w);
        }
        float sx = 0.f, sy = 0.f, sz = 0.f, sw = 0.f;
        #pragma unroll
        for (int c = 0; c < CC; ++c) {
            lg[c].x = __expf(lg[c].x - mx); sx += lg[c].x;
            lg[c].y = __expf(lg[c].y - my); sy += lg[c].y;
            lg[c].z = __expf(lg[c].z - mz); sz += lg[c].z;
            lg[c].w = __expf(lg[c].w - mw); sw += lg[c].w;
        }
        const float ix = 1.f/sx, iy = 1.f/sy, iz = 1.f/sz, iw = 1.f/sw;
        #pragma unroll
        for (int c = 0; c < CC; ++c)
            prob4[(b*CC + c)*16384 + hw4] =
                make_float4(lg[c].x*ix, lg[c].y*iy, lg[c].z*iz, lg[c].w*iw);
    }
}

// Deterministic block reduce into *dst (thread 0 writes).
__device__ __forceinline__ void block_reduce_write(float acc, float* dst) {
    #pragma unroll
    for (int o = 16; o > 0; o >>= 1)
        acc += __shfl_xor_sync(0xffffffffu, acc, o);
    __shared__ float swarp[8];
    if ((threadIdx.x & 31) == 0) swarp[threadIdx.x >> 5] = acc;
    __syncthreads();
    if (threadIdx.x == 0) {
        float s0 = 0.f;
        #pragma unroll
        for (int w = 0; w < 8; ++w) s0 += swarp[w];
        *dst = s0;
    }
}

// Merged column pass + FENCE-FREE last-block reduction. Writers use one
// release-atomic each (no per-block threadfence -> no L1 flush storm);
// only the elected block fences (one CCTL.IVALL) before the fixed-order sum.
__global__ void k_col(float* __restrict__ out) {
    __shared__ float s2[SROWS*JT];              // 24.5 KB; colout uses prefix
    float acc = 0.0f;

    if (blockIdx.x < NIN) {
        // ---------------- inside transform (sentinel-padded) ----------------
        const int jt  = blockIdx.x & (WW/JT - 1);
        const int bc  = blockIdx.x / (WW/JT);
        const int j0  = jt * JT;

        if (g_cnt[bc] != 0) {
            const int jj = threadIdx.x & (JT - 1);
            const int k0 = threadIdx.x / JT;    // 0..31

            for (int idx = threadIdx.x; idx < PAD*JT; idx += 256) {
                s2[idx] = 1e9f;
                s2[(PAD+HH)*JT + idx] = 1e9f;
            }
            #pragma unroll
            for (int m = 0; m < NR; ++m) {
                const int k = k0 + 32*m;
                const float g = (float)g_gin[(bc*HH + k)*WW + j0 + jj];
                s2[(k + PAD)*JT + jj] = g * g;
            }
            __syncthreads();

            float din2[NR], vlo[NR], vhi[NR];
            const float* plo = &s2[(k0 + PAD - 1)*JT + jj];
            const float* phi = &s2[(k0 + PAD + 1)*JT + jj];
            #pragma unroll
            for (int r = 0; r < NR; ++r) {
                din2[r] = s2[(k0 + 32*r + PAD)*JT + jj];
                vlo[r]  = plo[r*32*JT];
                vhi[r]  = phi[r*32*JT];
            }
            float mx = 0.f;
            #pragma unroll
            for (int r = 0; r < NR; ++r) mx = fmaxf(mx, din2[r]);

            for (int d = 1; d < HH; ++d) {
                const float dd2 = (float)(d * d);
                if (dd2 >= mx) break;
                #pragma unroll
                for (int r = 0; r < NR; ++r)
                    din2[r] = fminf(din2[r], dd2 + fminf(vlo[r], vhi[r]));
                plo -= JT; phi += JT;
                #pragma unroll
                for (int r = 0; r < NR; ++r) {
                    vlo[r] = plo[r*32*JT];
                    vhi[r] = phi[r*32*JT];
                }
                mx = 0.f;
                #pragma unroll
                for (int r = 0; r < NR; ++r) mx = fmaxf(mx, din2[r]);
            }

            #pragma unroll
            for (int r = 0; r < NR; ++r) {
                const int i = k0 + 32*r;
                acc += sqrtf(din2[r]) * g_prob[(bc*HH + i)*WW + j0 + jj];
            }
        }
    } else {
        // ------------- outside transform (collapsed) -------------
        const int bid = blockIdx.x - NIN;
        const int jt  = bid & (WW/JTO - 1);
        const int b   = bid / (WW/JTO);
        const int j0  = jt * JTO;

        int* si = (int*)s2;
        const int jj = threadIdx.x & (JTO - 1);
        const int k0 = threadIdx.x / JTO;

        #pragma unroll
        for (int m = 0; m < NRO; ++m) {
            const int k = k0 + 128*m;
            const unsigned v = g_tr[(b*HH + k)*WW + j0 + jj];
            const int rr = (int)(v & 1023u);
            si[k*JTO + jj] = (rr*rr*8) | (int)(v >> 10);   // r^2<<3 | t
        }
        __syncthreads();

        float dout2[NRO];
        int   tc[NRO], plo[NRO], phi[NRO];
        #pragma unroll
        for (int r = 0; r < NRO; ++r) {
            const int i  = k0 + 128*r;
            const int pv = si[i*JTO + jj];
            tc[r]    = pv & 7;
            dout2[r] = (float)(pv >> 3);
            plo[r]   = (i-1 >= 0) ? si[(i-1)*JTO + jj] : -1;
            phi[r]   = (i+1 < HH) ? si[(i+1)*JTO + jj] : -1;
        }
        float mx = 0.f;
        #pragma unroll
        for (int r = 0; r < NRO; ++r) mx = fmaxf(mx, dout2[r]);

        for (int d = 1; d < HH; ++d) {
            const float dd2 = (float)(d * d);
            if (dd2 >= mx) break;
            #pragma unroll
            for (int r = 0; r < NRO; ++r) {
                const float vl = (plo[r] < 0) ? 1e9f
                               : (((plo[r] & 7) == tc[r]) ? (float)(plo[r] >> 3) : 0.0f);
                const float vh = (phi[r] < 0) ? 1e9f
                               : (((phi[r] & 7) == tc[r]) ? (float)(phi[r] >> 3) : 0.0f);
                dout2[r] = fminf(dout2[r], dd2 + fminf(vl, vh));
            }
            #pragma unroll
            for (int r = 0; r < NRO; ++r) {
                const int i  = k0 + 128*r;
                const int lo = i - d - 1, hi = i + d + 1;
                plo[r] = (lo >= 0) ? si[lo*JTO + jj] : -1;
                phi[r] = (hi < HH) ? si[hi*JTO + jj] : -1;
            }
            mx = 0.f;
            #pragma unroll
            for (int r = 0; r < NRO; ++r) mx = fmaxf(mx, dout2[r]);
        }

        #pragma unroll
        for (int r = 0; r < NRO; ++r) {
            const int i = k0 + 128*r;
            const float p = g_prob[((b*CC + tc[r])*HH + i)*WW + j0 + jj];
            acc -= sqrtf(dout2[r]) * p;
        }
    }

    __syncthreads();
    block_reduce_write(acc, &g_part[blockIdx.x]);

    // ----- rendezvous: release-atomic arrival (NO per-block fence) -----
    __shared__ int s_last;
    if (threadIdx.x == 0) {
        int ticket;
        asm volatile("atom.add.release.gpu.global.s32 %0, [%1], 1;"
                     : "=r"(ticket) : "l"(&g_sem) : "memory");
        s_last = (ticket == NCOL - 1) ? 1 : 0;
        if (s_last) __threadfence();               // single acquire-side flush
    }
    __syncthreads();
    if (!s_last) return;

    // ----- elected block: deterministic fixed-order final sum -----
    float v = 0.0f;
    for (int k = threadIdx.x; k < NCOL; k += 256)
        v += g_part[k];
    #pragma unroll
    for (int o = 16; o > 0; o >>= 1)
        v += __shfl_xor_sync(0xffffffffu, v, o);
    __shared__ float fw[8];
    if ((threadIdx.x & 31) == 0) fw[threadIdx.x >> 5] = v;
    __syncthreads();
    if (threadIdx.x == 0) {
        float total = 0.f;
        #pragma unroll
        for (int w = 0; w < 8; ++w) total += fw[w];
        int n = 0;
        #pragma unroll
        for (int k = 0; k < BB*CC; ++k) n += (g_cnt[k] > 0) ? 1 : 0;
        const float nf = (n > 0) ? (float)n : 1.0f;
        out[0] = total / nf;
        #pragma unroll
        for (int k = 0; k < BB*CC; ++k) g_cnt[k] = 0;   // reset for replay
        g_sem = 0;
    }
}

// ---------------------------------------------------------------------------
extern "C" void kernel_launch(void* const* d_in, const int* in_sizes, int n_in,
                              void* d_out, int out_size) {
    const float* output = (const float*)d_in[0];   // [4,8,256,256] fp32
    const int*   target = (const int*)d_in[1];     // [4,256,256] int32
    float*       out    = (float*)d_out;           // scalar

    k_pre<<<NROWB + NSMB, 256>>>(target, output);
    k_col<<<NCOL, 256>>>(out);
}

// round 17
// speedup vs baseline: 1.2091x; 1.1297x over previous
#include <cuda_runtime.h>
#include <math.h>

#define BB 4
#define CC 8
#define HH 256
#define WW 256
#define INF_D 512
#define JT 8                          // columns per colin tile
#define NR 8                          // rows per colin thread (interleaved)
#define JTO 2                         // columns per colout tile
#define NRO 2                         // rows per colout thread
#define PAD 255                       // sentinel rows each side (colin)
#define SROWS (HH + 2*PAD)            // 766 padded rows
#define NIN   (BB*CC*(WW/JT))         // 1024 colin blocks
#define NOUT  (BB*(WW/JTO))           // 512 colout blocks
#define NCOL  (NIN + NOUT)            // 1536 k_col blocks
#define NROWB (BB*HH)                 // 1024 rowpass blocks
#define NSMB  ((BB*HH*WW)/(4*256))    // 256 softmax blocks

// Static device scratch. g_rowmask is fully overwritten every launch
// (non-atomic stores), so no cross-replay reset is needed anywhere.
__device__ unsigned short g_gin[BB*CC*HH*WW];   // 4 MB
__device__ unsigned short g_tr[BB*HH*WW];       // 0.5 MB: packed (t<<10 | r)
__device__ float          g_prob[BB*CC*HH*WW];  // 8 MB
__device__ unsigned       g_rowmask32[NROWB/4]; // per-row class-presence bytes

// ---------------------------------------------------------------------------
// Branchless nearest-set-bit query using per-(class,word) prefix/suffix LUT.
__device__ __forceinline__ int nb_lut(unsigned cur, int pref, int suff,
                                      int j, int bj) {
    const unsigned below = cur & (0xffffffffu >> (31 - bj));  // bits [0..bj]
    const unsigned above = cur >> bj;                         // bits [bj..31]
    const int dl = below ? (bj - (31 - __clz(below))) : (j - pref);
    const int dr = above ? (__ffs(above) - 1) : (suff - j);
    int d = dl < dr ? dl : dr;
    return d < INF_D ? d : INF_D;
}

// Pre-pass: blocks [0, NROWB) LUT row pass; [NROWB, +NSMB) float4 softmax.
// Also zeroes out[0] (d_out is poisoned) before k_col's atomics.
__global__ void k_pre(const int* __restrict__ target,
                      const float* __restrict__ output,
                      float* __restrict__ out) {
    if (blockIdx.x == NROWB && threadIdx.x == 0) out[0] = 0.0f;

    if (blockIdx.x < NROWB) {
        const int row = blockIdx.x;
        const int b   = row >> 8;
        const int h   = row & 255;
        const int j   = threadIdx.x;
        const int w   = j >> 5;
        const int ln  = j & 31;
        const int wj  = j >> 5;
        const int bj  = j & 31;

        __shared__ unsigned mask[CC][8];
        __shared__ int pf[CC][8], sf[CC][8], pfN[CC][8], sfN[CC][8];
        const int t = target[row * WW + j];

        #pragma unroll
        for (int c = 0; c < CC; ++c) {
            const unsigned m = __ballot_sync(0xffffffffu, t == c);
            if (ln == 0) mask[c][w] = m;
        }
        __syncthreads();

        // 64 threads build the prefix/suffix LUTs (masks + complements).
        if (j < 64) {
            const int c = j >> 3, ww = j & 7;
            int p = -1024, pn = -1024;
            for (int u = 0; u < ww; ++u) {
                const unsigned m = mask[c][u], mn = ~m;
                if (m)  p  = u*32 + 31 - __clz(m);
                if (mn) pn = u*32 + 31 - __clz(mn);
            }
            pf[c][ww] = p;  pfN[c][ww] = pn;
            int s = 1 << 20, sn = 1 << 20;
            for (int u = 7; u > ww; --u) {
                const unsigned m = mask[c][u], mn = ~m;
                if (m)  s  = u*32 + __ffs(m) - 1;
                if (mn) sn = u*32 + __ffs(mn) - 1;
            }
            sf[c][ww] = s;  sfN[c][ww] = sn;
        }
        __syncthreads();

        // r: nearest different-class column  (complement of mask[t])
        const int r = nb_lut(~mask[t][wj], pfN[t][wj], sfN[t][wj], j, bj);
        g_tr[row * WW + j] = (unsigned short)(r | (t << 10));

        #pragma unroll
        for (int c = 0; c < CC; ++c) {
            const int g = nb_lut(mask[c][wj], pf[c][wj], sf[c][wj], j, bj);
            g_gin[((b*CC + c)*HH + h)*WW + j] = (unsigned short)g;
        }

        // per-row presence byte, non-atomic (warp 0)
        if (j < 32) {
            unsigned nz = 0;
            if (j < CC) {
                unsigned o = 0;
                #pragma unroll
                for (int k = 0; k < 8; ++k) o |= mask[j][k];
                nz = (o != 0);
            }
            const unsigned bits = __ballot_sync(0xffffffffu, nz);
            if (j == 0)
                ((unsigned char*)g_rowmask32)[row] = (unsigned char)(bits & 0xffu);
        }
    } else {
        const int q   = (blockIdx.x - NROWB) * 256 + threadIdx.x;
        const int b   = q >> 14;
        const int hw4 = q & 16383;
        const float4* out4 = (const float4*)output;
        float4* prob4 = (float4*)g_prob;

        float4 lg[CC];
        float mx = -1e30f, my = -1e30f, mz = -1e30f, mw = -1e30f;
        #pragma unroll
        for (int c = 0; c < CC; ++c) {
            lg[c] = out4[(b*CC + c)*16384 + hw4];
            mx = fmaxf(mx, lg[c].x); my = fmaxf(my, lg[c].y);
            mz = fmaxf(mz, lg[c].z); mw = fmaxf(mw, lg[c].w);
        }
        float sx = 0.f, sy = 0.f, sz = 0.f, sw = 0.f;
        #pragma unroll
        for (int c = 0; c < CC; ++c) {
            lg[c].x = __expf(lg[c].x - mx); sx += lg[c].x;
            lg[c].y = __expf(lg[c].y - my); sy += lg[c].y;
            lg[c].z = __expf(lg[c].z - mz); sz += lg[c].z;
            lg[c].w = __expf(lg[c].w - mw); sw += lg[c].w;
        }
        const float ix = 1.f/sx, iy = 1.f/sy, iz = 1.f/sz, iw = 1.f/sw;
        #pragma unroll
        for (int c = 0; c < CC; ++c)
            prob4[(b*CC + c)*16384 + hw4] =
                make_float4(lg[c].x*ix, lg[c].y*iy, lg[c].z*iz, lg[c].w*iw);
    }
}

// Merged column pass; each block contributes partial * (1/n) via one
// atomicAdd on out[0] — no partial array, no finalization phase.
__global__ void k_col(float* __restrict__ out) {
    __shared__ float s2[SROWS*JT];              // 24.5 KB; colout uses prefix
    __shared__ int   s_pres[BB];

    // presence bits + n from g_rowmask (1 LDG/thread, smem OR)
    if (threadIdx.x < BB) s_pres[threadIdx.x] = 0;
    __syncthreads();
    {
        unsigned wv = g_rowmask32[threadIdx.x];          // rows 4t..4t+3
        wv |= wv >> 16; wv = (wv | (wv >> 8)) & 0xffu;
        atomicOr(&s_pres[threadIdx.x >> 6], (int)wv);    // batch = word>>6
    }
    __syncthreads();
    const int n_present = __popc(s_pres[0]) + __popc(s_pres[1])
                        + __popc(s_pres[2]) + __popc(s_pres[3]);
    const float inv_n = 1.0f / fmaxf((float)n_present, 1.0f);

    float acc = 0.0f;

    if (blockIdx.x < NIN) {
        // ---------------- inside transform (sentinel-padded) ----------------
        const int jt  = blockIdx.x & (WW/JT - 1);
        const int bc  = blockIdx.x / (WW/JT);
        const int j0  = jt * JT;

        if ((s_pres[bc >> 3] >> (bc & 7)) & 1) {
            const int jj = threadIdx.x & (JT - 1);
            const int k0 = threadIdx.x / JT;    // 0..31

            for (int idx = threadIdx.x; idx < PAD*JT; idx += 256) {
                s2[idx] = 1e9f;
                s2[(PAD+HH)*JT + idx] = 1e9f;
            }
            #pragma unroll
            for (int m = 0; m < NR; ++m) {
                const int k = k0 + 32*m;
                const float g = (float)g_gin[(bc*HH + k)*WW + j0 + jj];
                s2[(k + PAD)*JT + jj] = g * g;
            }
            __syncthreads();

            float din2[NR], vlo[NR], vhi[NR];
            const float* plo = &s2[(k0 + PAD - 1)*JT + jj];
            const float* phi = &s2[(k0 + PAD + 1)*JT + jj];
            #pragma unroll
            for (int r = 0; r < NR; ++r) {
                din2[r] = s2[(k0 + 32*r + PAD)*JT + jj];
                vlo[r]  = plo[r*32*JT];
                vhi[r]  = phi[r*32*JT];
            }
            float mx = 0.f;
            #pragma unroll
            for (int r = 0; r < NR; ++r) mx = fmaxf(mx, din2[r]);

            for (int d = 1; d < HH; ++d) {
                const float dd2 = (float)(d * d);
                if (dd2 >= mx) break;
                #pragma unroll
                for (int r = 0; r < NR; ++r)
                    din2[r] = fminf(din2[r], dd2 + fminf(vlo[r], vhi[r]));
                plo -= JT; phi += JT;
                #pragma unroll
                for (int r = 0; r < NR; ++r) {
                    vlo[r] = plo[r*32*JT];
                    vhi[r] = phi[r*32*JT];
                }
                mx = 0.f;
                #pragma unroll
                for (int r = 0; r < NR; ++r) mx = fmaxf(mx, din2[r]);
            }

            #pragma unroll
            for (int r = 0; r < NR; ++r) {
                const int i = k0 + 32*r;
                acc += sqrtf(din2[r]) * g_prob[(bc*HH + i)*WW + j0 + jj];
            }
        } else {
            return;                             // absent class: contributes 0
        }
    } else {
        // ------------- outside transform (collapsed) -------------
        const int bid = blockIdx.x - NIN;
        const int jt  = bid & (WW/JTO - 1);
        const int b   = bid / (WW/JTO);
        const int j0  = jt * JTO;

        int* si = (int*)s2;
        const int jj = threadIdx.x & (JTO - 1);
        const int k0 = threadIdx.x / JTO;

        #pragma unroll
        for (int m = 0; m < NRO; ++m) {
            const int k = k0 + 128*m;
            const unsigned v = g_tr[(b*HH + k)*WW + j0 + jj];
            const int rr = (int)(v & 1023u);
            si[k*JTO + jj] = (rr*rr*8) | (int)(v >> 10);   // r^2<<3 | t
        }
        __syncthreads();

        float dout2[NRO];
        int   tc[NRO], plo[NRO], phi[NRO];
        #pragma unroll
        for (int r = 0; r < NRO; ++r) {
            const int i  = k0 + 128*r;
            const int pv = si[i*JTO + jj];
            tc[r]    = pv & 7;
            dout2[r] = (float)(pv >> 3);
            plo[r]   = (i-1 >= 0) ? si[(i-1)*JTO + jj] : -1;
            phi[r]   = (i+1 < HH) ? si[(i+1)*JTO + jj] : -1;
        }
        float mx = 0.f;
        #pragma unroll
        for (int r = 0; r < NRO; ++r) mx = fmaxf(mx, dout2[r]);

        for (int d = 1; d < HH; ++d) {
            const float dd2 = (float)(d * d);
            if (dd2 >= mx) break;
            #pragma unroll
            for (int r = 0; r < NRO; ++r) {
                const float vl = (plo[r] < 0) ? 1e9f
                               : (((plo[r] & 7) == tc[r]) ? (float)(plo[r] >> 3) : 0.0f);
                const float vh = (phi[r] < 0) ? 1e9f
                               : (((phi[r] & 7) == tc[r]) ? (float)(phi[r] >> 3) : 0.0f);
                dout2[r] = fminf(dout2[r], dd2 + fminf(vl, vh));
            }
            #pragma unroll
            for (int r = 0; r < NRO; ++r) {
                const int i  = k0 + 128*r;
                const int lo = i - d - 1, hi = i + d + 1;
                plo[r] = (lo >= 0) ? si[lo*JTO + jj] : -1;
                phi[r] = (hi < HH) ? si[hi*JTO + jj] : -1;
            }
            mx = 0.f;
            #pragma unroll
            for (int r = 0; r < NRO; ++r) mx = fmaxf(mx, dout2[r]);
        }

        #pragma unroll
        for (int r = 0; r < NRO; ++r) {
            const int i = k0 + 128*r;
            const float p = g_prob[((b*CC + tc[r])*HH + i)*WW + j0 + jj];
            acc -= sqrtf(dout2[r]) * p;
        }
    }

    // block reduce + single scaled atomic contribution
    __syncthreads();
    #pragma unroll
    for (int o = 16; o > 0; o >>= 1)
        acc += __shfl_xor_sync(0xffffffffu, acc, o);
    __shared__ float swarp[8];
    if ((threadIdx.x & 31) == 0) swarp[threadIdx.x >> 5] = acc;
    __syncthreads();
    if (threadIdx.x == 0) {
        float s0 = 0.f;
        #pragma unroll
        for (int w = 0; w < 8; ++w) s0 += swarp[w];
        atomicAdd(out, s0 * inv_n);
    }
}

// ---------------------------------------------------------------------------
extern "C" void kernel_launch(void* const* d_in, const int* in_sizes, int n_in,
                              void* d_out, int out_size) {
    const float* output = (const float*)d_in[0];   // [4,8,256,256] fp32
    const int*   target = (const int*)d_in[1];     // [4,256,256] int32
    float*       out    = (float*)d_out;           // scalar

    k_pre<<<NROWB + NSMB, 256>>>(target, output, out);
    k_col<<<NCOL, 256>>>(out);
}